// round 15
// baseline (speedup 1.0000x reference)
#include <cuda_runtime.h>
#include <math.h>

#define Nn     16384
#define D_INc  256
#define HIDD   256
#define D_OUTc 256
#define Ff     8
#define Ll     4
#define IN_CH  272          // 2*8 + 256
#define GAMMAf 0.5f

// ---------------- device scratch (no allocations allowed) ----------------
__device__ __align__(16) float g_cs[2][Ll][Ff];
__device__ __align__(16) float g_Hm[Nn][16];      // cols 0-7: tri, 8-15: cl4

__device__ __forceinline__ float softplusf(float x) {
    return (x > 20.f) ? x : log1pf(expf(x));
}

__device__ __forceinline__ void red4(float* p, float a, float b, float c, float d) {
    asm volatile("red.global.add.v4.f32 [%0], {%1, %2, %3, %4};"
                 :: "l"(p), "f"(a), "f"(b), "f"(c), "f"(d) : "memory");
}

// packed dual-fp32 FMA (Blackwell f32x2) -------------------------------
#define FFMA2(acc, a, b) \
    asm("fma.rn.f32x2 %0, %1, %2, %0;" : "+l"(acc) : "l"(a), "l"(b))
#define DUP2(p, x) \
    asm("mov.b64 %0, {%1, %1};" : "=l"(p) : "r"(x))
#define UNPK2(lo, hi, p) \
    asm("mov.b64 {%0, %1}, %2;" : "=r"(lo), "=r"(hi) : "l"(p))

// register-free async gmem->smem 16B copy (LDGSTS)
#define CPA16(dst, src) do {                                              \
    unsigned _s = (unsigned)__cvta_generic_to_shared(dst);                \
    asm volatile("cp.async.cg.shared.global [%0], [%1], 16;"              \
                 :: "r"(_s), "l"(src));                                   \
} while (0)
#define CP_COMMIT() asm volatile("cp.async.commit_group;" ::: "memory")
#define CP_WAIT0()  asm volatile("cp.async.wait_group 0;" ::: "memory")

// ---------------- kernel 1: zero accumulator + filter traces ----------------
__global__ void init_kernel(const float* __restrict__ Wt,
                            const float* __restrict__ Wc,
                            const float* __restrict__ lg) {
    int i = blockIdx.x * blockDim.x + threadIdx.x;
    if (i < Nn * 4)
        ((float4*)g_Hm)[i] = make_float4(0.f, 0.f, 0.f, 0.f);

    if (blockIdx.x == 0 && threadIdx.x < 16) {
        int t = threadIdx.x;
        int which = t >> 3;
        int f = t & 7;
        int S = which ? 4 : 3;
        const float* W = which ? (Wc + f * 16) : (Wt + f * 9);

        float Wm[4][4], Sf[4][4];
        for (int a = 0; a < S; a++)
            for (int b = 0; b < S; b++)
                Wm[a][b] = softplusf(W[a * S + b]);
        for (int a = 0; a < S; a++)
            for (int b = 0; b < S; b++)
                Sf[a][b] = 0.5f * (Wm[a][b] + Wm[b][a]);
        for (int a = 0; a < S; a++) Sf[a][a] = 0.f;
        for (int a = 0; a < S; a++) {
            float rs = 0.f;
            for (int b = 0; b < S; b++) rs += Sf[a][b];
            float inv = 1.f / fmaxf(rs, 1e-12f);
            for (int b = 0; b < S; b++) Sf[a][b] *= inv;
        }
        float P[4][4], Q[4][4], tr[Ll];
        for (int a = 0; a < S; a++)
            for (int b = 0; b < S; b++) P[a][b] = Sf[a][b];
        for (int l = 0; l < Ll; l++) {
            if (l) {
                for (int a = 0; a < S; a++)
                    for (int b = 0; b < S; b++) {
                        float acc = 0.f;
                        for (int k = 0; k < S; k++) acc += P[a][k] * Sf[k][b];
                        Q[a][b] = acc;
                    }
                for (int a = 0; a < S; a++)
                    for (int b = 0; b < S; b++) P[a][b] = Q[a][b];
            }
            float s = 0.f;
            for (int a = 0; a < S; a++) s += P[a][a];
            tr[l] = s;
        }
        for (int l = 0; l < Ll; l++) {
            float coeff = powf(GAMMAf, (float)(l + 1)) * softplusf(lg[l]);
            g_cs[which][l][f] = tr[l] * coeff;
        }
    }
}

// ---------------- motif response (1 motif/thread) ----------------
template <int S>
__device__ __forceinline__ void motif_body(const float* __restrict__ A,
                                           const int* __restrict__ nodes,
                                           int M, int which, int bid) {
    int m = bid * 256 + threadIdx.x;
    if (m >= M) return;

    int nd[S];
#pragma unroll
    for (int i = 0; i < S; i++) nd[i] = nodes[m * S + i];

    float T[S][S];
#pragma unroll
    for (int i = 0; i < S; i++) {
        const float* rowp = A + (size_t)nd[i] * Nn;
#pragma unroll
        for (int j = 0; j < S; j++) T[i][j] = __ldg(rowp + nd[j]);
    }
#pragma unroll
    for (int i = 0; i < S; i++) {
        float rs = 0.f;
#pragma unroll
        for (int j = 0; j < S; j++) rs += T[i][j];
        float inv = 1.f / fmaxf(rs, 1e-12f);
#pragma unroll
        for (int j = 0; j < S; j++) T[i][j] *= inv;
    }

    float P[S][S], Q[S][S], tr[Ll];
#pragma unroll
    for (int i = 0; i < S; i++)
#pragma unroll
        for (int j = 0; j < S; j++) P[i][j] = T[i][j];
    {
        float s = 0.f;
#pragma unroll
        for (int i = 0; i < S; i++) s += P[i][i];
        tr[0] = s;
    }
#pragma unroll
    for (int l = 1; l < Ll; l++) {
#pragma unroll
        for (int i = 0; i < S; i++)
#pragma unroll
            for (int j = 0; j < S; j++) {
                float a = 0.f;
#pragma unroll
                for (int k = 0; k < S; k++) a += P[i][k] * T[k][j];
                Q[i][j] = a;
            }
        float s = 0.f;
#pragma unroll
        for (int i = 0; i < S; i++) {
#pragma unroll
            for (int j = 0; j < S; j++) P[i][j] = Q[i][j];
            s += P[i][i];
        }
        tr[l] = s;
    }

    float sims[Ff];
#pragma unroll
    for (int f = 0; f < Ff; f++) {
        float s = 0.f;
#pragma unroll
        for (int l = 0; l < Ll; l++) s += tr[l] * g_cs[which][l][f];
        sims[f] = s;
    }
    float mx = sims[0];
#pragma unroll
    for (int f = 1; f < Ff; f++) mx = fmaxf(mx, sims[f]);
    float e[Ff], es = 0.f;
#pragma unroll
    for (int f = 0; f < Ff; f++) { e[f] = expf(sims[f] - mx); es += e[f]; }
    float invs = 1.f / es;
    const float invS = 1.f / (float)S;
    float cb[Ff];
#pragma unroll
    for (int f = 0; f < Ff; f++) cb[f] = e[f] * invs * sims[f] * invS;

    int off = which * 8;
#pragma unroll
    for (int i = 0; i < S; i++) {
        float* p = &g_Hm[nd[i]][off];
        red4(p,     cb[0], cb[1], cb[2], cb[3]);
        red4(p + 4, cb[4], cb[5], cb[6], cb[7]);
    }
}

__global__ void motif_all_kernel(const float* __restrict__ A,
                                 const int* __restrict__ nt, int Mt, int nb3,
                                 const int* __restrict__ nc, int Mc) {
    if ((int)blockIdx.x < nb3)
        motif_body<3>(A, nt, Mt, 0, blockIdx.x);
    else
        motif_body<4>(A, nc, Mc, 1, blockIdx.x - nb3);
}

// ---------------- fused concat + LN + MLP ----------------
// Occupancy push: 256 threads (8 warps), warp owns 32 cols, ALL 32 rows.
// Thread tile: 16 rows x 2 cols (acc = 16 u64). Same cp.async structure.
#define ROWS  32
#define TPB   256
#define BK    8
#define XS    36                  // padded row stride in sXT

__global__ __launch_bounds__(TPB, 3) void mlp_kernel(
    const float* __restrict__ H_in, const float* __restrict__ ln_g,
    const float* __restrict__ ln_b,
    const float* __restrict__ W1, const float* __restrict__ b1,
    const float* __restrict__ W2, const float* __restrict__ b2,
    float* __restrict__ out) {
    __shared__ float sXT[IN_CH * XS];      // [k][row] transposed acts
    __shared__ float sW[2][BK * HIDD];     // double-buffered W tile (block-wide)

    const int tid  = threadIdx.x;
    const int warp = tid >> 5;
    const int lane = tid & 31;
    const int rbase = blockIdx.x * ROWS;

    const int rg = lane >> 4;              // 0-1  -> rows rg*16 .. +16
    const int cg = lane & 15;              // 0-15 -> 2 cols each
    const int r0 = rg * 16;
    const int cb = warp * 32 + cg * 2;     // global output col base (2 cols)

    // block-wide async fetch of one BK-row W tile (8KB, 2 x 16B per thread)
#define CPA_TILE(Wp, kbase, BUF)                                             \
    {                                                                        \
        _Pragma("unroll")                                                    \
        for (int q = 0; q < 2; q++) {                                        \
            int p = q * TPB + tid;                                           \
            int kk = p >> 6, cc = (p & 63) << 2;                             \
            CPA16(&sW[BUF][kk * HIDD + cc],                                  \
                  &Wp[(size_t)((kbase) + kk) * HIDD + cc]);                  \
        }                                                                    \
        CP_COMMIT();                                                         \
    }
#define COMPUTE_TILE(K0, BUF)                                                \
    {                                                                        \
        _Pragma("unroll")                                                    \
        for (int kk = 0; kk < BK; kk++) {                                    \
            const float* xb = &sXT[(K0 + kk) * XS + r0];                     \
            ulonglong2 xA = *(const ulonglong2*)xb;         /* rows 0-3 */   \
            ulonglong2 xB = *(const ulonglong2*)(xb + 4);   /* rows 4-7 */   \
            ulonglong2 xC = *(const ulonglong2*)(xb + 8);   /* rows 8-11 */  \
            ulonglong2 xD = *(const ulonglong2*)(xb + 12);  /* rows 12-15 */ \
            float2 wv = *(const float2*)&sW[BUF][kk * HIDD + cb];            \
            unsigned long long wd0, wd1;                                     \
            DUP2(wd0, __float_as_uint(wv.x));                                \
            DUP2(wd1, __float_as_uint(wv.y));                                \
            FFMA2(acc[0][0], xA.x, wd0); FFMA2(acc[0][1], xA.x, wd1);        \
            FFMA2(acc[1][0], xA.y, wd0); FFMA2(acc[1][1], xA.y, wd1);        \
            FFMA2(acc[2][0], xB.x, wd0); FFMA2(acc[2][1], xB.x, wd1);        \
            FFMA2(acc[3][0], xB.y, wd0); FFMA2(acc[3][1], xB.y, wd1);        \
            FFMA2(acc[4][0], xC.x, wd0); FFMA2(acc[4][1], xC.x, wd1);        \
            FFMA2(acc[5][0], xC.y, wd0); FFMA2(acc[5][1], xC.y, wd1);        \
            FFMA2(acc[6][0], xD.x, wd0); FFMA2(acc[6][1], xD.x, wd1);        \
            FFMA2(acc[7][0], xD.y, wd0); FFMA2(acc[7][1], xD.y, wd1);        \
        }                                                                    \
    }

    // kick off W1 tile 0 fetch — latency hides under LN
    CPA_TILE(W1, 0, 0);

    // ---- LN: warp handles 4 rows; single gmem read ----
    {
        const int rl = warp * 4;
#pragma unroll
        for (int i = 0; i < 4; i++) {
            int r = rl + i;
            int grow = rbase + r;
            const float* hrow = H_in + (size_t)grow * D_INc;
            float vloc[9];
            float s = 0.f, s2 = 0.f;
#pragma unroll
            for (int q = 0; q < 9; q++) {
                int c = lane + q * 32;
                if (c < IN_CH) {
                    float v = (c < 16) ? g_Hm[grow][c] : __ldg(hrow + (c - 16));
                    vloc[q] = v;
                    s += v; s2 += v * v;
                }
            }
#pragma unroll
            for (int o = 16; o; o >>= 1) {
                s  += __shfl_xor_sync(0xffffffffu, s, o);
                s2 += __shfl_xor_sync(0xffffffffu, s2, o);
            }
            float mu = s * (1.f / IN_CH);
            float var = s2 * (1.f / IN_CH) - mu * mu;
            float rstd = rsqrtf(var + 1e-5f);
#pragma unroll
            for (int q = 0; q < 9; q++) {
                int c = lane + q * 32;
                if (c < IN_CH)
                    sXT[c * XS + r] = (vloc[q] - mu) * rstd * ln_g[c] + ln_b[c];
            }
        }
    }
    CP_WAIT0();
    __syncthreads();

    unsigned long long acc[8][2];      // [row-pair][col]
#pragma unroll
    for (int i = 0; i < 8; i++) { acc[i][0] = 0ULL; acc[i][1] = 0ULL; }

    // ---- GEMM1: x(32x272) @ W1(272x256) ----
    {
        const int NT = IN_CH / BK;       // 34
        for (int t = 0; t < NT; t++) {
            if (t + 1 < NT) CPA_TILE(W1, (t + 1) * BK, (t + 1) & 1);
            COMPUTE_TILE(t * BK, t & 1);
            if (t + 1 < NT) CP_WAIT0();
            __syncthreads();
        }
    }

    // prefetch W2 tile 0 — hides under GELU math
    CPA_TILE(W2, 0, 0);

    // ---- bias + exact GELU -> transposed hidden into sXT ----
    {
        const float2 bv = *(const float2*)&b1[cb];
        const float bbv[2] = {bv.x, bv.y};
#pragma unroll
        for (int rp = 0; rp < 8; rp++) {
#pragma unroll
            for (int j = 0; j < 2; j++) {
                unsigned lo, hi;
                UNPK2(lo, hi, acc[rp][j]);
                float x0 = __uint_as_float(lo) + bbv[j];
                float x1 = __uint_as_float(hi) + bbv[j];
                x0 = 0.5f * x0 * (1.f + erff(x0 * 0.7071067811865475f));
                x1 = 0.5f * x1 * (1.f + erff(x1 * 0.7071067811865475f));
                *(float2*)&sXT[(cb + j) * XS + r0 + rp * 2] = make_float2(x0, x1);
                acc[rp][j] = 0ULL;
            }
        }
    }
    CP_WAIT0();
    __syncthreads();

    // ---- GEMM2: h(32x256) @ W2(256x256) ----
    {
        const int NT = HIDD / BK;        // 32
        for (int t = 0; t < NT; t++) {
            if (t + 1 < NT) CPA_TILE(W2, (t + 1) * BK, (t + 1) & 1);
            COMPUTE_TILE(t * BK, t & 1);
            if (t + 1 < NT) CP_WAIT0();
            __syncthreads();
        }
    }

    // ---- bias + store ----
    {
        const float2 bv = *(const float2*)&b2[cb];
#pragma unroll
        for (int rp = 0; rp < 8; rp++) {
            unsigned lo0, hi0, lo1, hi1;
            UNPK2(lo0, hi0, acc[rp][0]);
            UNPK2(lo1, hi1, acc[rp][1]);
            size_t rowA = (size_t)(rbase + r0 + rp * 2) * D_OUTc;
            *(float2*)&out[rowA + cb] =
                make_float2(__uint_as_float(lo0) + bv.x,
                            __uint_as_float(lo1) + bv.y);
            *(float2*)&out[rowA + D_OUTc + cb] =
                make_float2(__uint_as_float(hi0) + bv.x,
                            __uint_as_float(hi1) + bv.y);
        }
    }
}

// ---------------- launch ----------------
extern "C" void kernel_launch(void* const* d_in, const int* in_sizes, int n_in,
                              void* d_out, int out_size) {
    const float* A       = (const float*)d_in[0];
    const float* H_in    = (const float*)d_in[1];
    const float* Wt      = (const float*)d_in[2];
    const float* Wc      = (const float*)d_in[3];
    const float* lg      = (const float*)d_in[4];
    const float* ln_g    = (const float*)d_in[5];
    const float* ln_b    = (const float*)d_in[6];
    const float* W1      = (const float*)d_in[7];
    const float* b1      = (const float*)d_in[8];
    const float* W2      = (const float*)d_in[9];
    const float* b2      = (const float*)d_in[10];
    const int* nodes_tri = (const int*)d_in[11];
    const int* nodes_cl4 = (const int*)d_in[12];
    float* out = (float*)d_out;

    int M_tri = in_sizes[11] / 3;
    int M_cl4 = in_sizes[12] / 4;
    int nb3 = (M_tri + 255) / 256;
    int nb4 = (M_cl4 + 255) / 256;

    init_kernel<<<(Nn * 4 + 255) / 256, 256>>>(Wt, Wc, lg);
    motif_all_kernel<<<nb3 + nb4, 256>>>(A, nodes_tri, M_tri, nb3, nodes_cl4, M_cl4);
    mlp_kernel<<<Nn / ROWS, TPB>>>(H_in, ln_g, ln_b, W1, b1, W2, b2, out);
}